// round 13
// baseline (speedup 1.0000x reference)
#include <cuda_runtime.h>

#define S_LEN   2048
#define NCH     64
#define NB      16
#define CHUNK   128
#define NSC     (S_LEN / CHUNK)        // 16 sample-chunks
#define PLI_THREADS 512
#define NWARPS  (PLI_THREADS / 32)
#define FFT_THREADS 256

// Scratch (static __device__ allocation — allowed by harness rules)
__device__ float2 g_analytic[NB * NCH * S_LEN];   // 16 MB
__device__ int    g_cnt[NB * NCH * NCH];          // 256 KB of int counters

// smem index padding for the FFT buffers: breaks the 8-way (M=2) and 4-way
// (M=8) store conflicts of the small-M Stockham stages down to <=2-way.
__device__ __forceinline__ int SPAD(int i) { return i + (i >> 3); }
#define FFT_PADDED 2304                 // 2048 + 2048/8

// ---------------------------------------------------------------------------
// Radix-4 Stockham autosort FFT pieces (N = 2048 = 2 * 4^5).
// DIF formulation; natural-order in, natural-order out; ping-pong buffers.
// ---------------------------------------------------------------------------
__device__ __forceinline__ float2 cmul(float2 a, float2 b) {
    return make_float2(fmaf(a.x, b.x, -a.y * b.y),
                       fmaf(a.x, b.y,  a.y * b.x));
}

// radix-2 first stage (forward): l = 1024, m = 1
__device__ __forceinline__ void stage_r2_fwd(const float2* __restrict__ src,
                                             float2* __restrict__ dst,
                                             const float2* __restrict__ tw,
                                             int tid) {
    #pragma unroll 4
    for (int p = tid; p < 1024; p += FFT_THREADS) {
        float2 w = tw[p];                       // exp(-2*pi*i p/2048)
        float2 a = src[SPAD(p)];
        float2 b = src[SPAD(p + 1024)];
        dst[SPAD(2 * p)]     = make_float2(a.x + b.x, a.y + b.y);
        dst[SPAD(2 * p + 1)] = cmul(w, make_float2(a.x - b.x, a.y - b.y));
    }
}

// radix-4 stage: L * M * 4 == 2048
template<int L, int LOG2M, bool INV>
__device__ __forceinline__ void stage_r4(const float2* __restrict__ src,
                                         float2* __restrict__ dst,
                                         const float2* __restrict__ tw,
                                         int tid) {
    constexpr int M   = 1 << LOG2M;
    constexpr int TWS = 512 / L;                // twiddle stride
    #pragma unroll
    for (int t = tid; t < 512; t += FFT_THREADS) {
        const int p = t >> LOG2M;
        const int q = t & (M - 1);
        const int ib = q + M * p;               // == t
        float2 a = src[SPAD(ib)];
        float2 b = src[SPAD(ib + M * L)];
        float2 c = src[SPAD(ib + 2 * M * L)];
        float2 d = src[SPAD(ib + 3 * M * L)];

        float2 w1 = tw[p * TWS];                // exp(-2*pi*i p/(4L))
        float2 w2 = tw[2 * p * TWS];
        if (INV) { w1.y = -w1.y; w2.y = -w2.y; }
        float2 w3 = cmul(w1, w2);

        float2 t0 = make_float2(a.x + c.x, a.y + c.y);
        float2 t1 = make_float2(a.x - c.x, a.y - c.y);
        float2 t2 = make_float2(b.x + d.x, b.y + d.y);
        float2 e  = make_float2(b.x - d.x, b.y - d.y);
        float2 t3 = INV ? make_float2(-e.y,  e.x)
                        : make_float2( e.y, -e.x);

        const int ob = q + 4 * M * p;
        dst[SPAD(ob)]         = make_float2(t0.x + t2.x, t0.y + t2.y);
        dst[SPAD(ob + M)]     = cmul(w1, make_float2(t1.x + t3.x, t1.y + t3.y));
        dst[SPAD(ob + 2 * M)] = cmul(w2, make_float2(t0.x - t2.x, t0.y - t2.y));
        dst[SPAD(ob + 3 * M)] = cmul(w3, make_float2(t1.x - t3.x, t1.y - t3.y));
    }
}

// 5 inverse radix-4 stages (after the fused degenerate stage-1).
// X -> Y -> X -> Y -> X -> Y : result lands in Y. Ends with __syncthreads.
__device__ __forceinline__ void ifft_tail(float2* __restrict__ X,
                                          float2* __restrict__ Y,
                                          const float2* __restrict__ tw,
                                          int tid) {
    stage_r4<256, 1, true>(X, Y, tw, tid);  __syncthreads();
    stage_r4< 64, 3, true>(Y, X, tw, tid);  __syncthreads();
    stage_r4< 16, 5, true>(X, Y, tw, tid);  __syncthreads();
    stage_r4<  4, 7, true>(Y, X, tw, tid);  __syncthreads();
    stage_r4<  1, 9, true>(X, Y, tw, tid);  __syncthreads();
}

// ---------------------------------------------------------------------------
// Kernel 1: Hilbert analytic signal, 2 channels per block (R11 anchor:
// 256 threads, 3 buffers, sincosf twiddles, fused degenerate inverse
// stage-1, fused g_cnt zeroing). ONE change: SPAD-padded FFT buffers
// (dynamic smem, 62 KB) to kill the small-M stage store conflicts.
// ---------------------------------------------------------------------------
__global__ __launch_bounds__(FFT_THREADS)
void hilbert_kernel(const float* __restrict__ x) {
    extern __shared__ float2 smem[];
    float2* A  = smem;                          // FFT_PADDED
    float2* B  = smem + FFT_PADDED;             // FFT_PADDED
    float2* Cb = smem + 2 * FFT_PADDED;         // FFT_PADDED
    float2* tw = smem + 3 * FFT_PADDED;         // 1024 (unpadded: broadcast)

    const int bc  = blockIdx.x;               // 0..511 (channel pair)
    const int tid = threadIdx.x;
    const int ch0 = 2 * bc;

    // fused counter zeroing (visible to pli via stream ordering)
    if (tid < 128) g_cnt[bc * 128 + tid] = 0;

    const float* __restrict__ x0 = x + (size_t)ch0 * S_LEN;
    const float* __restrict__ x1 = x0 + S_LEN;

    // twiddles: tw[k] = exp(-2*pi*i*k / S)
    for (int k = tid; k < S_LEN / 2; k += FFT_THREADS) {
        float ang = (-6.283185307179586f / (float)S_LEN) * (float)k;
        float sn, cs;
        sincosf(ang, &sn, &cs);
        tw[k] = make_float2(cs, sn);
    }
    // pack two real channels into one complex signal
    for (int i = tid; i < S_LEN; i += FFT_THREADS)
        A[SPAD(i)] = make_float2(x0[i], x1[i]);
    __syncthreads();

    // forward FFT: A -> B -> A -> B -> A -> B -> A (result in A, natural)
    stage_r2_fwd(A, B, tw, tid);               __syncthreads();
    stage_r4<256, 1, false>(B, A, tw, tid);    __syncthreads();
    stage_r4< 64, 3, false>(A, B, tw, tid);    __syncthreads();
    stage_r4< 16, 5, false>(B, A, tw, tid);    __syncthreads();
    stage_r4<  4, 7, false>(A, B, tw, tid);    __syncthreads();
    stage_r4<  1, 9, false>(B, A, tw, tid);    __syncthreads();

    // Unpack + Hilbert filter + fused degenerate inverse stage-1:
    //   G0[k] = h[k]*(Z[k] + conj(Z[N-k]))        (ch0 spectrum)
    //   G1[k] = h[k]*(-i)*(Z[k] - conj(Z[N-k]))   (ch1 spectrum)
    // Zero for k > N/2  =>  inverse stage-1 (radix-2) degenerates:
    //   p>=1 : dst[2p] = G[p], dst[2p+1] = conj(w_p)*G[p]
    //   p==0 : dst[0] = G[0]+G[1024], dst[1] = G[0]-G[1024]
    for (int p = tid; p < 1024; p += FFT_THREADS) {
        float2 zk = A[SPAD(p)];
        float2 zm = A[SPAD((S_LEN - p) & (S_LEN - 1))];
        float  h  = (p == 0) ? 1.0f : 2.0f;
        float2 G0 = make_float2(h * (zk.x + zm.x),  h * (zk.y - zm.y));
        float2 G1 = make_float2(h * (zk.y + zm.y), -h * (zk.x - zm.x));
        if (p == 0) {
            float2 z2 = A[SPAD(1024)];  // G0[1024]=2*z2.x ; G1[1024]=2*z2.y
            B [SPAD(0)] = make_float2(G0.x + 2.0f * z2.x, G0.y);
            B [SPAD(1)] = make_float2(G0.x - 2.0f * z2.x, G0.y);
            Cb[SPAD(0)] = make_float2(G1.x + 2.0f * z2.y, G1.y);
            Cb[SPAD(1)] = make_float2(G1.x - 2.0f * z2.y, G1.y);
        } else {
            float2 wc = tw[p]; wc.y = -wc.y;
            B [SPAD(2 * p)]     = G0;
            B [SPAD(2 * p + 1)] = cmul(wc, G0);
            Cb[SPAD(2 * p)]     = G1;
            Cb[SPAD(2 * p + 1)] = cmul(wc, G1);
        }
    }
    __syncthreads();

    // inverse chain 0 (B <-> A, result in A): analytic ch0
    ifft_tail(B, A, tw, tid);
    float2* __restrict__ d0 = g_analytic + (size_t)ch0 * S_LEN;
    for (int i = tid; i < S_LEN; i += FFT_THREADS)
        d0[i] = A[SPAD(i)];
    __syncthreads();

    // inverse chain 1 (Cb <-> B, result in B): analytic ch1
    ifft_tail(Cb, B, tw, tid);
    float2* __restrict__ d1 = d0 + S_LEN;
    for (int i = tid; i < S_LEN; i += FFT_THREADS)
        d1[i] = B[SPAD(i)];
}

// ---------------------------------------------------------------------------
// Kernel 2: pairwise sign counting (unchanged from R11's winning version).
// cross = y_i*x_j - x_i*y_j ; acc += signbit (alu pipe, overlaps fma pipe);
// HW REDUX warp-sum; lane-0 atomics.
// ---------------------------------------------------------------------------
__global__ __launch_bounds__(PLI_THREADS)
void pli_kernel() {
    extern __shared__ float2 sdata[];                 // [NCH][CHUNK]
    const int sc  = blockIdx.x;
    const int b   = blockIdx.y;
    const int tid = threadIdx.x;

    const float4* gsrc = reinterpret_cast<const float4*>(g_analytic);
    float4* ssh = reinterpret_cast<float4*>(sdata);
    for (int k = tid; k < NCH * (CHUNK / 2); k += PLI_THREADS) {
        int c  = k / (CHUNK / 2);
        int sp = k - c * (CHUNK / 2);
        size_t gi = (((size_t)(b * NCH + c)) * S_LEN + (size_t)sc * CHUNK) / 2 + sp;
        ssh[c * (CHUNK / 2) + sp] = gsrc[gi];
    }
    __syncthreads();

    const int warp = tid >> 5;
    const int lane = tid & 31;

    for (int t = warp; t < 136; t += NWARPS) {
        int ti = 0, rem = t;
        while (rem >= (16 - ti)) { rem -= (16 - ti); ti++; }
        int tj = ti + rem;

        const float2* rowi = sdata + (ti * 4) * CHUNK;
        const float2* rowj = sdata + (tj * 4) * CHUNK;

        unsigned acc[16];
        #pragma unroll
        for (int q = 0; q < 16; q++) acc[q] = 0u;

        #pragma unroll
        for (int it = 0; it < CHUNK / 32; it++) {
            int s = it * 32 + lane;
            float2 ai[4], aj[4];
            #pragma unroll
            for (int a = 0; a < 4; a++) ai[a] = rowi[a * CHUNK + s];
            #pragma unroll
            for (int a = 0; a < 4; a++) aj[a] = rowj[a * CHUNK + s];

            #pragma unroll
            for (int a = 0; a < 4; a++) {
                #pragma unroll
                for (int c2 = 0; c2 < 4; c2++) {
                    float p     = ai[a].x * aj[c2].y;
                    float cross = fmaf(ai[a].y, aj[c2].x, -p);
                    // negative (sign bit) => sin < 0 ; exact zeros measure-zero
                    acc[a * 4 + c2] += __float_as_uint(cross) >> 31;
                }
            }
        }

        #pragma unroll
        for (int q = 0; q < 16; q++)
            acc[q] = __reduce_add_sync(0xffffffffu, acc[q]);

        if (lane == 0) {
            #pragma unroll
            for (int a = 0; a < 4; a++) {
                #pragma unroll
                for (int c2 = 0; c2 < 4; c2++) {
                    atomicAdd(&g_cnt[(b * NCH + ti * 4 + a) * NCH + tj * 4 + c2],
                              (int)acc[a * 4 + c2]);
                }
            }
        }
    }
}

// ---------------------------------------------------------------------------
// Kernel 3: finalize |2c - S|/S ; zero diagonal; mirror i>j.
// (c = negative-count N; |2N - S| == |sumsign| since sumsign = S - 2N.)
// ---------------------------------------------------------------------------
__global__ void finalize_kernel(float* __restrict__ out) {
    int idx = blockIdx.x * blockDim.x + threadIdx.x;
    if (idx >= NB * NCH * NCH) return;
    int b = idx >> 12;
    int i = (idx >> 6) & 63;
    int j = idx & 63;
    float v = 0.0f;
    if (i != j) {
        int c = (i < j) ? g_cnt[(b * NCH + i) * NCH + j]
                        : g_cnt[(b * NCH + j) * NCH + i];
        v = fabsf(2.0f * (float)c - (float)S_LEN) * (1.0f / (float)S_LEN);
    }
    out[idx] = v;
}

// ---------------------------------------------------------------------------
extern "C" void kernel_launch(void* const* d_in, const int* in_sizes, int n_in,
                              void* d_out, int out_size) {
    const float* x = (const float*)d_in[0];
    float* out = (float*)d_out;
    (void)in_sizes; (void)n_in; (void)out_size;

    const int fft_smem = (3 * FFT_PADDED + 1024) * (int)sizeof(float2); // 63488
    const int pli_smem = NCH * CHUNK * (int)sizeof(float2);             // 65536
    cudaFuncSetAttribute(hilbert_kernel,
                         cudaFuncAttributeMaxDynamicSharedMemorySize, fft_smem);
    cudaFuncSetAttribute(pli_kernel,
                         cudaFuncAttributeMaxDynamicSharedMemorySize, pli_smem);

    hilbert_kernel<<<NB * NCH / 2, FFT_THREADS, fft_smem>>>(x);
    pli_kernel<<<dim3(NSC, NB), PLI_THREADS, pli_smem>>>();
    finalize_kernel<<<(NB * NCH * NCH + 255) / 256, 256>>>(out);
}

// round 14
// speedup vs baseline: 1.1313x; 1.1313x over previous
#include <cuda_runtime.h>

#define S_LEN   2048
#define NCH     64
#define NB      16
#define CHUNK   128
#define NSC     (S_LEN / CHUNK)        // 16 sample-chunks
#define PLI_THREADS 512
#define NWARPS  (PLI_THREADS / 32)
#define FFT_THREADS 512

// Scratch (static __device__ allocation — allowed by harness rules)
__device__ float2 g_analytic[NB * NCH * S_LEN];   // 16 MB
__device__ int    g_cnt[NB * NCH * NCH];          // 256 KB of int counters

// ---------------------------------------------------------------------------
// Radix-4 Stockham autosort FFT pieces (N = 2048 = 2 * 4^5).
// DIF formulation; natural-order in, natural-order out; ping-pong buffers.
// ---------------------------------------------------------------------------
__device__ __forceinline__ float2 cmul(float2 a, float2 b) {
    return make_float2(fmaf(a.x, b.x, -a.y * b.y),
                       fmaf(a.x, b.y,  a.y * b.x));
}

// radix-2 first stage (forward): l = 1024, m = 1
__device__ __forceinline__ void stage_r2_fwd(const float2* __restrict__ src,
                                             float2* __restrict__ dst,
                                             const float2* __restrict__ tw,
                                             int tid) {
    #pragma unroll
    for (int p = tid; p < 1024; p += FFT_THREADS) {
        float2 w = tw[p];                       // exp(-2*pi*i p/2048)
        float2 a = src[p];
        float2 b = src[p + 1024];
        dst[2 * p]     = make_float2(a.x + b.x, a.y + b.y);
        dst[2 * p + 1] = cmul(w, make_float2(a.x - b.x, a.y - b.y));
    }
}

// radix-4 stage: L * M * 4 == 2048
template<int L, int LOG2M, bool INV>
__device__ __forceinline__ void stage_r4(const float2* __restrict__ src,
                                         float2* __restrict__ dst,
                                         const float2* __restrict__ tw,
                                         int tid) {
    constexpr int M   = 1 << LOG2M;
    constexpr int TWS = 512 / L;                // twiddle stride
    #pragma unroll
    for (int t = tid; t < 512; t += FFT_THREADS) {
        const int p = t >> LOG2M;
        const int q = t & (M - 1);
        const int ib = q + M * p;               // == t
        float2 a = src[ib];
        float2 b = src[ib + M * L];
        float2 c = src[ib + 2 * M * L];
        float2 d = src[ib + 3 * M * L];

        float2 w1 = tw[p * TWS];                // exp(-2*pi*i p/(4L))
        float2 w2 = tw[2 * p * TWS];
        if (INV) { w1.y = -w1.y; w2.y = -w2.y; }
        float2 w3 = cmul(w1, w2);

        float2 t0 = make_float2(a.x + c.x, a.y + c.y);
        float2 t1 = make_float2(a.x - c.x, a.y - c.y);
        float2 t2 = make_float2(b.x + d.x, b.y + d.y);
        float2 e  = make_float2(b.x - d.x, b.y - d.y);
        float2 t3 = INV ? make_float2(-e.y,  e.x)
                        : make_float2( e.y, -e.x);

        const int ob = q + 4 * M * p;
        dst[ob]         = make_float2(t0.x + t2.x, t0.y + t2.y);
        dst[ob + M]     = cmul(w1, make_float2(t1.x + t3.x, t1.y + t3.y));
        dst[ob + 2 * M] = cmul(w2, make_float2(t0.x - t2.x, t0.y - t2.y));
        dst[ob + 3 * M] = cmul(w3, make_float2(t1.x - t3.x, t1.y - t3.y));
    }
}

// 5 inverse radix-4 stages (after the fused degenerate stage-1).
// X -> Y -> X -> Y -> X -> Y : result lands in Y. Ends with __syncthreads.
__device__ __forceinline__ void ifft_tail(float2* __restrict__ X,
                                          float2* __restrict__ Y,
                                          const float2* __restrict__ tw,
                                          int tid) {
    stage_r4<256, 1, true>(X, Y, tw, tid);  __syncthreads();
    stage_r4< 64, 3, true>(Y, X, tw, tid);  __syncthreads();
    stage_r4< 16, 5, true>(X, Y, tw, tid);  __syncthreads();
    stage_r4<  4, 7, true>(Y, X, tw, tid);  __syncthreads();
    stage_r4<  1, 9, true>(X, Y, tw, tid);  __syncthreads();
}

// ---------------------------------------------------------------------------
// Kernel 1: Hilbert analytic signal, 2 channels per block (R11 anchor
// structure: 3 unpadded static smem buffers, sincosf twiddles, fused
// degenerate inverse stage-1, fused g_cnt zeroing). ONE change vs R11:
// FFT_THREADS 256 -> 512 (1 butterfly/thread/stage; 2 blocks/SM x 16 warps
// = 32 warps resident vs 24 — attacks the latency-bound sync chain).
// ---------------------------------------------------------------------------
__global__ __launch_bounds__(FFT_THREADS)
void hilbert_kernel(const float* __restrict__ x) {
    __shared__ float2 A   [S_LEN];
    __shared__ float2 B   [S_LEN];
    __shared__ float2 Cb  [S_LEN];
    __shared__ float2 tw  [S_LEN / 2];

    const int bc  = blockIdx.x;               // 0..511 (channel pair)
    const int tid = threadIdx.x;
    const int ch0 = 2 * bc;

    // fused counter zeroing (visible to pli via stream ordering)
    if (tid < 128) g_cnt[bc * 128 + tid] = 0;

    const float* __restrict__ x0 = x + (size_t)ch0 * S_LEN;
    const float* __restrict__ x1 = x0 + S_LEN;

    // twiddles: tw[k] = exp(-2*pi*i*k / S)
    for (int k = tid; k < S_LEN / 2; k += FFT_THREADS) {
        float ang = (-6.283185307179586f / (float)S_LEN) * (float)k;
        float sn, cs;
        sincosf(ang, &sn, &cs);
        tw[k] = make_float2(cs, sn);
    }
    // pack two real channels into one complex signal
    for (int i = tid; i < S_LEN; i += FFT_THREADS)
        A[i] = make_float2(x0[i], x1[i]);
    __syncthreads();

    // forward FFT: A -> B -> A -> B -> A -> B -> A (result in A, natural)
    stage_r2_fwd(A, B, tw, tid);               __syncthreads();
    stage_r4<256, 1, false>(B, A, tw, tid);    __syncthreads();
    stage_r4< 64, 3, false>(A, B, tw, tid);    __syncthreads();
    stage_r4< 16, 5, false>(B, A, tw, tid);    __syncthreads();
    stage_r4<  4, 7, false>(A, B, tw, tid);    __syncthreads();
    stage_r4<  1, 9, false>(B, A, tw, tid);    __syncthreads();

    // Unpack + Hilbert filter + fused degenerate inverse stage-1:
    //   G0[k] = h[k]*(Z[k] + conj(Z[N-k]))        (ch0 spectrum)
    //   G1[k] = h[k]*(-i)*(Z[k] - conj(Z[N-k]))   (ch1 spectrum)
    // Zero for k > N/2  =>  inverse stage-1 (radix-2) degenerates:
    //   p>=1 : dst[2p] = G[p], dst[2p+1] = conj(w_p)*G[p]
    //   p==0 : dst[0] = G[0]+G[1024], dst[1] = G[0]-G[1024]
    for (int p = tid; p < 1024; p += FFT_THREADS) {
        float2 zk = A[p];
        float2 zm = A[(S_LEN - p) & (S_LEN - 1)];
        float  h  = (p == 0) ? 1.0f : 2.0f;
        float2 G0 = make_float2(h * (zk.x + zm.x),  h * (zk.y - zm.y));
        float2 G1 = make_float2(h * (zk.y + zm.y), -h * (zk.x - zm.x));
        if (p == 0) {
            float2 z2 = A[1024];    // G0[1024] = 2*z2.x ; G1[1024] = 2*z2.y
            B [0] = make_float2(G0.x + 2.0f * z2.x, G0.y);
            B [1] = make_float2(G0.x - 2.0f * z2.x, G0.y);
            Cb[0] = make_float2(G1.x + 2.0f * z2.y, G1.y);
            Cb[1] = make_float2(G1.x - 2.0f * z2.y, G1.y);
        } else {
            float2 wc = tw[p]; wc.y = -wc.y;
            B [2 * p]     = G0;
            B [2 * p + 1] = cmul(wc, G0);
            Cb[2 * p]     = G1;
            Cb[2 * p + 1] = cmul(wc, G1);
        }
    }
    __syncthreads();

    // inverse chain 0 (B <-> A, result in A): analytic ch0
    ifft_tail(B, A, tw, tid);
    float2* __restrict__ d0 = g_analytic + (size_t)ch0 * S_LEN;
    for (int i = tid; i < S_LEN; i += FFT_THREADS)
        d0[i] = A[i];
    __syncthreads();

    // inverse chain 1 (Cb <-> B, result in B): analytic ch1
    ifft_tail(Cb, B, tw, tid);
    float2* __restrict__ d1 = d0 + S_LEN;
    for (int i = tid; i < S_LEN; i += FFT_THREADS)
        d1[i] = B[i];
}

// ---------------------------------------------------------------------------
// Kernel 2: pairwise sign counting (unchanged from R11's winning version).
// cross = y_i*x_j - x_i*y_j ; acc += signbit (alu pipe, overlaps fma pipe);
// HW REDUX warp-sum; lane-0 atomics.
// ---------------------------------------------------------------------------
__global__ __launch_bounds__(PLI_THREADS)
void pli_kernel() {
    extern __shared__ float2 sdata[];                 // [NCH][CHUNK]
    const int sc  = blockIdx.x;
    const int b   = blockIdx.y;
    const int tid = threadIdx.x;

    const float4* gsrc = reinterpret_cast<const float4*>(g_analytic);
    float4* ssh = reinterpret_cast<float4*>(sdata);
    for (int k = tid; k < NCH * (CHUNK / 2); k += PLI_THREADS) {
        int c  = k / (CHUNK / 2);
        int sp = k - c * (CHUNK / 2);
        size_t gi = (((size_t)(b * NCH + c)) * S_LEN + (size_t)sc * CHUNK) / 2 + sp;
        ssh[c * (CHUNK / 2) + sp] = gsrc[gi];
    }
    __syncthreads();

    const int warp = tid >> 5;
    const int lane = tid & 31;

    for (int t = warp; t < 136; t += NWARPS) {
        int ti = 0, rem = t;
        while (rem >= (16 - ti)) { rem -= (16 - ti); ti++; }
        int tj = ti + rem;

        const float2* rowi = sdata + (ti * 4) * CHUNK;
        const float2* rowj = sdata + (tj * 4) * CHUNK;

        unsigned acc[16];
        #pragma unroll
        for (int q = 0; q < 16; q++) acc[q] = 0u;

        #pragma unroll
        for (int it = 0; it < CHUNK / 32; it++) {
            int s = it * 32 + lane;
            float2 ai[4], aj[4];
            #pragma unroll
            for (int a = 0; a < 4; a++) ai[a] = rowi[a * CHUNK + s];
            #pragma unroll
            for (int a = 0; a < 4; a++) aj[a] = rowj[a * CHUNK + s];

            #pragma unroll
            for (int a = 0; a < 4; a++) {
                #pragma unroll
                for (int c2 = 0; c2 < 4; c2++) {
                    float p     = ai[a].x * aj[c2].y;
                    float cross = fmaf(ai[a].y, aj[c2].x, -p);
                    // negative (sign bit) => sin < 0 ; exact zeros measure-zero
                    acc[a * 4 + c2] += __float_as_uint(cross) >> 31;
                }
            }
        }

        #pragma unroll
        for (int q = 0; q < 16; q++)
            acc[q] = __reduce_add_sync(0xffffffffu, acc[q]);

        if (lane == 0) {
            #pragma unroll
            for (int a = 0; a < 4; a++) {
                #pragma unroll
                for (int c2 = 0; c2 < 4; c2++) {
                    atomicAdd(&g_cnt[(b * NCH + ti * 4 + a) * NCH + tj * 4 + c2],
                              (int)acc[a * 4 + c2]);
                }
            }
        }
    }
}

// ---------------------------------------------------------------------------
// Kernel 3: finalize |2c - S|/S ; zero diagonal; mirror i>j.
// (c = negative-count N; |2N - S| == |sumsign| since sumsign = S - 2N.)
// ---------------------------------------------------------------------------
__global__ void finalize_kernel(float* __restrict__ out) {
    int idx = blockIdx.x * blockDim.x + threadIdx.x;
    if (idx >= NB * NCH * NCH) return;
    int b = idx >> 12;
    int i = (idx >> 6) & 63;
    int j = idx & 63;
    float v = 0.0f;
    if (i != j) {
        int c = (i < j) ? g_cnt[(b * NCH + i) * NCH + j]
                        : g_cnt[(b * NCH + j) * NCH + i];
        v = fabsf(2.0f * (float)c - (float)S_LEN) * (1.0f / (float)S_LEN);
    }
    out[idx] = v;
}

// ---------------------------------------------------------------------------
extern "C" void kernel_launch(void* const* d_in, const int* in_sizes, int n_in,
                              void* d_out, int out_size) {
    const float* x = (const float*)d_in[0];
    float* out = (float*)d_out;
    (void)in_sizes; (void)n_in; (void)out_size;

    const int pli_smem = NCH * CHUNK * (int)sizeof(float2);   // 64 KB
    cudaFuncSetAttribute(pli_kernel,
                         cudaFuncAttributeMaxDynamicSharedMemorySize, pli_smem);

    hilbert_kernel<<<NB * NCH / 2, FFT_THREADS>>>(x);
    pli_kernel<<<dim3(NSC, NB), PLI_THREADS, pli_smem>>>();
    finalize_kernel<<<(NB * NCH * NCH + 255) / 256, 256>>>(out);
}

// round 15
// speedup vs baseline: 1.2662x; 1.1193x over previous
#include <cuda_runtime.h>

#define S_LEN   2048
#define NCH     64
#define NB      16
#define CHUNK   128
#define NSC     (S_LEN / CHUNK)        // 16 sample-chunks
#define PLI_THREADS 512
#define NWARPS  (PLI_THREADS / 32)
#define FFT_THREADS 512

// Scratch (static __device__ allocation — allowed by harness rules)
__device__ float2 g_analytic[NB * NCH * S_LEN];   // 16 MB
__device__ int    g_cnt[NB * NCH * NCH];          // 256 KB of int counters

// ---------------------------------------------------------------------------
// Radix-4 Stockham autosort FFT pieces (N = 2048 = 2 * 4^5).
// DIF formulation; natural-order in, natural-order out; ping-pong buffers.
// ---------------------------------------------------------------------------
__device__ __forceinline__ float2 cmul(float2 a, float2 b) {
    return make_float2(fmaf(a.x, b.x, -a.y * b.y),
                       fmaf(a.x, b.y,  a.y * b.x));
}

// radix-2 first stage (forward): l = 1024, m = 1
__device__ __forceinline__ void stage_r2_fwd(const float2* __restrict__ src,
                                             float2* __restrict__ dst,
                                             const float2* __restrict__ tw,
                                             int tid) {
    #pragma unroll
    for (int p = tid; p < 1024; p += FFT_THREADS) {
        float2 w = tw[p];                       // exp(-2*pi*i p/2048)
        float2 a = src[p];
        float2 b = src[p + 1024];
        dst[2 * p]     = make_float2(a.x + b.x, a.y + b.y);
        dst[2 * p + 1] = cmul(w, make_float2(a.x - b.x, a.y - b.y));
    }
}

// radix-4 stage: L * M * 4 == 2048
template<int L, int LOG2M, bool INV>
__device__ __forceinline__ void stage_r4(const float2* __restrict__ src,
                                         float2* __restrict__ dst,
                                         const float2* __restrict__ tw,
                                         int tid) {
    constexpr int M   = 1 << LOG2M;
    constexpr int TWS = 512 / L;                // twiddle stride
    #pragma unroll
    for (int t = tid; t < 512; t += FFT_THREADS) {
        const int p = t >> LOG2M;
        const int q = t & (M - 1);
        const int ib = q + M * p;               // == t
        float2 a = src[ib];
        float2 b = src[ib + M * L];
        float2 c = src[ib + 2 * M * L];
        float2 d = src[ib + 3 * M * L];

        float2 w1 = tw[p * TWS];                // exp(-2*pi*i p/(4L))
        float2 w2 = tw[2 * p * TWS];
        if (INV) { w1.y = -w1.y; w2.y = -w2.y; }
        float2 w3 = cmul(w1, w2);

        float2 t0 = make_float2(a.x + c.x, a.y + c.y);
        float2 t1 = make_float2(a.x - c.x, a.y - c.y);
        float2 t2 = make_float2(b.x + d.x, b.y + d.y);
        float2 e  = make_float2(b.x - d.x, b.y - d.y);
        float2 t3 = INV ? make_float2(-e.y,  e.x)
                        : make_float2( e.y, -e.x);

        const int ob = q + 4 * M * p;
        dst[ob]         = make_float2(t0.x + t2.x, t0.y + t2.y);
        dst[ob + M]     = cmul(w1, make_float2(t1.x + t3.x, t1.y + t3.y));
        dst[ob + 2 * M] = cmul(w2, make_float2(t0.x - t2.x, t0.y - t2.y));
        dst[ob + 3 * M] = cmul(w3, make_float2(t1.x - t3.x, t1.y - t3.y));
    }
}

// 5 inverse radix-4 stages (after the fused degenerate stage-1).
// X -> Y -> X -> Y -> X -> Y : result lands in Y. Ends with __syncthreads.
__device__ __forceinline__ void ifft_tail(float2* __restrict__ X,
                                          float2* __restrict__ Y,
                                          const float2* __restrict__ tw,
                                          int tid) {
    stage_r4<256, 1, true>(X, Y, tw, tid);  __syncthreads();
    stage_r4< 64, 3, true>(Y, X, tw, tid);  __syncthreads();
    stage_r4< 16, 5, true>(X, Y, tw, tid);  __syncthreads();
    stage_r4<  4, 7, true>(Y, X, tw, tid);  __syncthreads();
    stage_r4<  1, 9, true>(X, Y, tw, tid);  __syncthreads();
}

// ---------------------------------------------------------------------------
// Kernel 1: Hilbert analytic signal, 2 channels per block, ONE inverse FFT.
//   W = IFFT(h/N ⊙ FFT(x0 + i*x1)) = analytic(x0) + i*analytic(x1)
//     = (x0 - Hx1) + i*(Hx0 + x1)
// so with the known inputs:  Hx0 = Im W - x1 ,  Hx1 = x0 - Re W.
// No spectrum unpack, no second inverse chain. The filtered spectrum is
// zero above N/2, so the proven degenerate inverse stage-1 fusion applies.
// Normalization (1/N and the 1/2 of h) is folded into the filter since the
// time-domain separation needs exact scale. Two smem buffers + twiddles
// (40 KB). Also zeroes g_cnt (stream-ordered before pli).
// ---------------------------------------------------------------------------
__global__ __launch_bounds__(FFT_THREADS)
void hilbert_kernel(const float* __restrict__ x) {
    __shared__ float2 A [S_LEN];
    __shared__ float2 B [S_LEN];
    __shared__ float2 tw[S_LEN / 2];

    const int bc  = blockIdx.x;               // 0..511 (channel pair)
    const int tid = threadIdx.x;
    const int ch0 = 2 * bc;

    // fused counter zeroing (visible to pli via stream ordering)
    if (tid < 128) g_cnt[bc * 128 + tid] = 0;

    const float* __restrict__ x0 = x + (size_t)ch0 * S_LEN;
    const float* __restrict__ x1 = x0 + S_LEN;

    // twiddles: tw[k] = exp(-2*pi*i*k / S)
    for (int k = tid; k < S_LEN / 2; k += FFT_THREADS) {
        float ang = (-6.283185307179586f / (float)S_LEN) * (float)k;
        float sn, cs;
        sincosf(ang, &sn, &cs);
        tw[k] = make_float2(cs, sn);
    }
    // pack two real channels into one complex signal
    for (int i = tid; i < S_LEN; i += FFT_THREADS)
        A[i] = make_float2(x0[i], x1[i]);
    __syncthreads();

    // forward FFT: A -> B -> A -> B -> A -> B -> A (result in A, natural)
    stage_r2_fwd(A, B, tw, tid);               __syncthreads();
    stage_r4<256, 1, false>(B, A, tw, tid);    __syncthreads();
    stage_r4< 64, 3, false>(A, B, tw, tid);    __syncthreads();
    stage_r4< 16, 5, false>(B, A, tw, tid);    __syncthreads();
    stage_r4<  4, 7, false>(A, B, tw, tid);    __syncthreads();
    stage_r4<  1, 9, false>(B, A, tw, tid);    __syncthreads();

    // Filter (h/N) + fused degenerate inverse stage-1 (spectrum zero above
    // N/2):  p>=1 : dst[2p] = W[p], dst[2p+1] = conj(w_p)*W[p]
    //        p==0 : dst[0] = W[0]+W[1024], dst[1] = W[0]-W[1024]
    // W[k] = Z[k] * h[k]/N :  k=0,1024 -> 1/2048 ;  k=1..1023 -> 2/2048.
    const float S0 = 1.0f / 2048.0f;
    const float S1 = 2.0f / 2048.0f;
    for (int p = tid; p < 1024; p += FFT_THREADS) {
        if (p == 0) {
            float2 z0 = A[0];
            float2 zn = A[1024];
            float2 W0 = make_float2(z0.x * S0, z0.y * S0);
            float2 Wn = make_float2(zn.x * S0, zn.y * S0);
            B[0] = make_float2(W0.x + Wn.x, W0.y + Wn.y);
            B[1] = make_float2(W0.x - Wn.x, W0.y - Wn.y);
        } else {
            float2 zp = A[p];
            float2 Wp = make_float2(zp.x * S1, zp.y * S1);
            float2 wc = tw[p]; wc.y = -wc.y;
            B[2 * p]     = Wp;
            B[2 * p + 1] = cmul(wc, Wp);
        }
    }
    __syncthreads();

    // single inverse chain (B <-> A, result in A): W in time domain
    ifft_tail(B, A, tw, tid);

    // time-domain separation:
    //   analytic0 = (x0, Im W - x1) ; analytic1 = (x1, x0 - Re W)
    float2* __restrict__ d0 = g_analytic + (size_t)ch0 * S_LEN;
    float2* __restrict__ d1 = d0 + S_LEN;
    for (int i = tid; i < S_LEN; i += FFT_THREADS) {
        float2 W  = A[i];
        float  r0 = x0[i];
        float  r1 = x1[i];
        d0[i] = make_float2(r0, W.y - r1);
        d1[i] = make_float2(r1, r0 - W.x);
    }
}

// ---------------------------------------------------------------------------
// Kernel 2: pairwise sign counting (unchanged from R11's winning version).
// cross = y_i*x_j - x_i*y_j ; acc += signbit (alu pipe, overlaps fma pipe);
// HW REDUX warp-sum; lane-0 atomics.
// ---------------------------------------------------------------------------
__global__ __launch_bounds__(PLI_THREADS)
void pli_kernel() {
    extern __shared__ float2 sdata[];                 // [NCH][CHUNK]
    const int sc  = blockIdx.x;
    const int b   = blockIdx.y;
    const int tid = threadIdx.x;

    const float4* gsrc = reinterpret_cast<const float4*>(g_analytic);
    float4* ssh = reinterpret_cast<float4*>(sdata);
    for (int k = tid; k < NCH * (CHUNK / 2); k += PLI_THREADS) {
        int c  = k / (CHUNK / 2);
        int sp = k - c * (CHUNK / 2);
        size_t gi = (((size_t)(b * NCH + c)) * S_LEN + (size_t)sc * CHUNK) / 2 + sp;
        ssh[c * (CHUNK / 2) + sp] = gsrc[gi];
    }
    __syncthreads();

    const int warp = tid >> 5;
    const int lane = tid & 31;

    for (int t = warp; t < 136; t += NWARPS) {
        int ti = 0, rem = t;
        while (rem >= (16 - ti)) { rem -= (16 - ti); ti++; }
        int tj = ti + rem;

        const float2* rowi = sdata + (ti * 4) * CHUNK;
        const float2* rowj = sdata + (tj * 4) * CHUNK;

        unsigned acc[16];
        #pragma unroll
        for (int q = 0; q < 16; q++) acc[q] = 0u;

        #pragma unroll
        for (int it = 0; it < CHUNK / 32; it++) {
            int s = it * 32 + lane;
            float2 ai[4], aj[4];
            #pragma unroll
            for (int a = 0; a < 4; a++) ai[a] = rowi[a * CHUNK + s];
            #pragma unroll
            for (int a = 0; a < 4; a++) aj[a] = rowj[a * CHUNK + s];

            #pragma unroll
            for (int a = 0; a < 4; a++) {
                #pragma unroll
                for (int c2 = 0; c2 < 4; c2++) {
                    float p     = ai[a].x * aj[c2].y;
                    float cross = fmaf(ai[a].y, aj[c2].x, -p);
                    // negative (sign bit) => sin < 0 ; exact zeros measure-zero
                    acc[a * 4 + c2] += __float_as_uint(cross) >> 31;
                }
            }
        }

        #pragma unroll
        for (int q = 0; q < 16; q++)
            acc[q] = __reduce_add_sync(0xffffffffu, acc[q]);

        if (lane == 0) {
            #pragma unroll
            for (int a = 0; a < 4; a++) {
                #pragma unroll
                for (int c2 = 0; c2 < 4; c2++) {
                    atomicAdd(&g_cnt[(b * NCH + ti * 4 + a) * NCH + tj * 4 + c2],
                              (int)acc[a * 4 + c2]);
                }
            }
        }
    }
}

// ---------------------------------------------------------------------------
// Kernel 3: finalize |2c - S|/S ; zero diagonal; mirror i>j.
// (c = negative-count N; |2N - S| == |sumsign| since sumsign = S - 2N.)
// ---------------------------------------------------------------------------
__global__ void finalize_kernel(float* __restrict__ out) {
    int idx = blockIdx.x * blockDim.x + threadIdx.x;
    if (idx >= NB * NCH * NCH) return;
    int b = idx >> 12;
    int i = (idx >> 6) & 63;
    int j = idx & 63;
    float v = 0.0f;
    if (i != j) {
        int c = (i < j) ? g_cnt[(b * NCH + i) * NCH + j]
                        : g_cnt[(b * NCH + j) * NCH + i];
        v = fabsf(2.0f * (float)c - (float)S_LEN) * (1.0f / (float)S_LEN);
    }
    out[idx] = v;
}

// ---------------------------------------------------------------------------
extern "C" void kernel_launch(void* const* d_in, const int* in_sizes, int n_in,
                              void* d_out, int out_size) {
    const float* x = (const float*)d_in[0];
    float* out = (float*)d_out;
    (void)in_sizes; (void)n_in; (void)out_size;

    const int pli_smem = NCH * CHUNK * (int)sizeof(float2);   // 64 KB
    cudaFuncSetAttribute(pli_kernel,
                         cudaFuncAttributeMaxDynamicSharedMemorySize, pli_smem);

    hilbert_kernel<<<NB * NCH / 2, FFT_THREADS>>>(x);
    pli_kernel<<<dim3(NSC, NB), PLI_THREADS, pli_smem>>>();
    finalize_kernel<<<(NB * NCH * NCH + 255) / 256, 256>>>(out);
}